// round 11
// baseline (speedup 1.0000x reference)
#include <cuda_runtime.h>
#include <cstdint>

#define BB 8
#define CC 64
#define HH 64
#define WW 64
#define OO 64
#define HWT (HH*WW)
#define JJ 27

// tf32 round (keeps top 10 mantissa bits)
__device__ __forceinline__ float tf32r(float x) {
    unsigned u;
    asm("cvt.rna.tf32.f32 %0, %1;" : "=r"(u) : "f"(x));
    return __uint_as_float(u);
}

// mma.sync m16n8k8 tf32: D += A*B (fp32 accum)
#define MMA8(D, A0, A1, A2, A3, B0, B1)                                   \
    asm volatile("mma.sync.aligned.m16n8k8.row.col.f32.tf32.tf32.f32 "     \
        "{%0,%1,%2,%3}, {%4,%5,%6,%7}, {%8,%9}, {%0,%1,%2,%3};"            \
        : "+f"((D)[0]), "+f"((D)[1]), "+f"((D)[2]), "+f"((D)[3])           \
        : "r"(A0), "r"(A1), "r"(A2), "r"(A3), "r"(B0), "r"(B1))

// Scratch (device globals: no allocation allowed)
__device__ float  g_nhwc2[BB*HH*WW*128];   // concat(feat, degrad) NHWC, 128 ch
__device__ float  g_om[BB*JJ*HWT];         // offset/mask conv output
__device__ float  g_omp[2*BB*JJ*HWT];      // om partials (split-K halves)
__device__ float  g_outp[2*BB*OO*HWT];     // deform partials (split-K halves)
__device__ __align__(16) float2 g_wtB[9*2*2048];     // deform weights hi/lo B-frags
__device__ __align__(16) float2 g_omB[9*2*8*4*32];   // om weights hi-only B-frags

// ---------------------------------------------------------------------------
// Kernel 1: NCHW feat+degrad -> g_nhwc2[b][y][x][128]. One block per (b,h).
// ---------------------------------------------------------------------------
__global__ __launch_bounds__(256) void transpose_nhwc2(const float* __restrict__ feat,
                                                       const float* __restrict__ deg) {
    int bh = blockIdx.x;
    int b = bh / HH, h = bh % HH;
    __shared__ float tile[128][WW + 1];
    for (int i = threadIdx.x; i < 128 * WW; i += 256) {
        int c = i >> 6, w = i & 63;
        const float* src = (c < 64) ? feat : deg;
        tile[c][w] = src[(((size_t)b * 64 + (c & 63)) * HH + h) * WW + w];
    }
    __syncthreads();
    float* dst = g_nhwc2 + (((size_t)b * HH + h) * WW) * 128;
    for (int i = threadIdx.x; i < 128 * WW; i += 256) {
        int w = i >> 7, c = i & 127;
        dst[w * 128 + c] = tile[c][w];
    }
}

// ---------------------------------------------------------------------------
// Kernel 2a: deform weight (O,C,3,3) -> g_wtB (m16n8k8 B-frag layout, hi/lo).
// ---------------------------------------------------------------------------
__global__ void transpose_w(const float* __restrict__ w) {
    int i = blockIdx.x * blockDim.x + threadIdx.x;
    if (i >= 9*2*2048) return;
    int k = i / 4096;
    int r = i % 4096;
    int h = r >> 11;
    int e = r & 2047;
    int lane = e & 31;
    int frag = e >> 5;
    int nt = frag & 7, s = frag >> 3;
    int o = nt*8 + (lane >> 2);
    int c0 = s*8 + (lane & 3)*2;
    float v0 = w[(o*CC + c0)*9 + k];
    float v1 = w[(o*CC + c0 + 1)*9 + k];
    float h0 = tf32r(v0), h1 = tf32r(v1);
    g_wtB[i] = h ? make_float2(tf32r(v0 - h0), tf32r(v1 - h1))
                 : make_float2(h0, h1);
}

// ---------------------------------------------------------------------------
// Kernel 2b: om_weight (27,128,3,3) -> g_omB, N padded to 32, hi-only tf32.
// ---------------------------------------------------------------------------
__global__ void transpose_omw(const float* __restrict__ omw) {
    int i = blockIdx.x * blockDim.x + threadIdx.x;
    if (i >= 9*2*8*4*32) return;
    int lane = i & 31;
    int r = i >> 5;
    int nt = r & 3;  r >>= 2;
    int s = r & 7;   r >>= 3;
    int c64 = r & 1;
    int k = r >> 1;
    int j = nt*8 + (lane >> 2);
    int c = c64*64 + s*8 + (lane & 3)*2;
    float v0 = 0.f, v1 = 0.f;
    if (j < JJ) {
        v0 = omw[(j*128 + c)*9 + k];
        v1 = omw[(j*128 + c + 1)*9 + k];
    }
    g_omB[i] = make_float2(tf32r(v0), tf32r(v1));
}

// ---------------------------------------------------------------------------
// Kernel 3: om conv, single-pass tf32, SPLIT-K over taps (blockIdx.y half).
// B read directly from gmem (L1-resident). Partials -> g_omp.
// ---------------------------------------------------------------------------
#define OM_TOT 33792

__global__ __launch_bounds__(256) void om_gemm() {
    extern __shared__ char sm[];
    int bi = blockIdx.x;
    int kh = blockIdx.y;
    int b  = bi >> 5;
    int tY = (bi >> 2) & 7;
    int tX = bi & 3;
    int kstart = kh ? 4 : 0, kend = kh ? 9 : 4;

    int t = threadIdx.x;
    int lane = t & 31;
    int wrp = t >> 5;
    int wm = wrp >> 1, wn = wrp & 1;

    int q = t & 15, px8 = t >> 4;
    int s_smp = q >> 1;
    int lnc = (q & 1) * 2;

    const float4* img = (const float4*)(g_nhwc2 + (size_t)b * HWT * 128);

    float d[2][2][4];
#pragma unroll
    for (int i = 0; i < 2; i++)
#pragma unroll
        for (int j = 0; j < 2; j++)
#pragma unroll
            for (int e = 0; e < 4; e++) d[i][j][e] = 0.f;

    for (int k = kstart; k < kend; k++) {
        int ky = k / 3 - 1, kx = k % 3 - 1;
#pragma unroll
        for (int c64 = 0; c64 < 2; c64++) {
            if (k != kstart || c64) __syncthreads();

            // A tile: shifted window, hi only, fragment-layout STS
#pragma unroll
            for (int j = 0; j < 8; j++) {
                int px = px8 * 8 + j;
                int gy = tY * 8 + (px >> 4), gx = tX * 16 + (px & 15);
                int yy = gy + ky, xx = gx + kx;
                float4 v = make_float4(0.f, 0.f, 0.f, 0.f);
                if (yy >= 0 && yy < HH && xx >= 0 && xx < WW)
                    v = img[(yy * WW + xx) * 32 + c64 * 16 + q];
                float h0 = tf32r(v.x), h1 = tf32r(v.y);
                float h2 = tf32r(v.z), h3 = tf32r(v.w);

                int mt = px >> 4;
                int r = px & 7;
                int high = (px >> 3) & 1;
                int fo = (mt * 8 + s_smp) * 528 + high * 8;
                int la = (r * 4 + lnc) * 16;
                *(float2*)(sm + fo + la)      = make_float2(h0, h1);
                *(float2*)(sm + fo + la + 16) = make_float2(h2, h3);
            }
            __syncthreads();

            // GEMM, B direct from gmem
            const char* Ah = sm;
            const uint2* Bg = (const uint2*)(g_omB + (size_t)(k*2 + c64) * 1024);
#pragma unroll
            for (int s = 0; s < 8; s++) {
                int f0 = ((wm * 2 + 0) * 8 + s) * 528 + lane * 16;
                int f1 = ((wm * 2 + 1) * 8 + s) * 528 + lane * 16;
                uint4 ah0 = *(const uint4*)(Ah + f0);
                uint4 ah1 = *(const uint4*)(Ah + f1);
#pragma unroll
                for (int nt = 0; nt < 2; nt++) {
                    uint2 bh = __ldg(&Bg[(s * 4 + wn * 2 + nt) * 32 + lane]);
                    MMA8(d[0][nt], ah0.x, ah0.z, ah0.y, ah0.w, bh.x, bh.y);
                    MMA8(d[1][nt], ah1.x, ah1.z, ah1.y, ah1.w, bh.x, bh.y);
                }
            }
        }
    }

    // Epilogue: write partials (no bias; reduce adds it). Skip padded j.
#pragma unroll
    for (int mi = 0; mi < 2; mi++) {
        int pxb = (wm * 2 + mi) * 16 + (lane >> 2);
        int gy0 = tY * 8 + (pxb >> 4), gx0 = tX * 16 + (pxb & 15);
        int px2 = pxb + 8;
        int gy1 = tY * 8 + (px2 >> 4), gx1 = tX * 16 + (px2 & 15);
#pragma unroll
        for (int nt = 0; nt < 2; nt++) {
            int j = wn * 16 + nt * 8 + (lane & 3) * 2;
            size_t base = (((size_t)kh * BB + b) * JJ + j) * HWT;
            if (j < JJ) {
                g_omp[base + gy0 * WW + gx0] = d[mi][nt][0];
                g_omp[base + gy1 * WW + gx1] = d[mi][nt][2];
            }
            if (j + 1 < JJ) {
                g_omp[base + HWT + gy0 * WW + gx0] = d[mi][nt][1];
                g_omp[base + HWT + gy1 * WW + gx1] = d[mi][nt][3];
            }
        }
    }
}

// ---------------------------------------------------------------------------
// Kernel 3b: g_om = g_omp[0] + g_omp[1] + bias
// ---------------------------------------------------------------------------
__global__ __launch_bounds__(256) void reduce_om() {
    // bias folded via separate arg-free path: bias passed through const mem below
}
__global__ __launch_bounds__(256) void reduce_om2(const float* __restrict__ omb) {
    int i = blockIdx.x * 256 + threadIdx.x;
    if (i >= BB * JJ * 1024) return;
    int j = (i >> 10) % JJ;
    float bias = omb[j];
    float4 a = ((const float4*)g_omp)[i];
    float4 c = ((const float4*)g_omp)[i + BB * JJ * 1024];
    ((float4*)g_om)[i] = make_float4(a.x + c.x + bias, a.y + c.y + bias,
                                     a.z + c.z + bias, a.w + c.w + bias);
}

// ---------------------------------------------------------------------------
// Kernel 4: deformable conv, 3-pass tf32, SPLIT-K over taps, B from gmem.
// Partials -> g_outp.
// ---------------------------------------------------------------------------
#define SM_PQ  0
#define SM_WQ  2048
#define SM_AHI 4096
#define SM_ALO (SM_AHI + 33792)
#define SM_TOT (SM_ALO + 33792)

__global__ __launch_bounds__(256, 3) void deform() {
    extern __shared__ char sm[];
    int bi = blockIdx.x;
    int kh = blockIdx.y;
    int b  = bi >> 5;
    int tY = (bi >> 2) & 7;
    int tX = bi & 3;
    int kstart = kh ? 4 : 0, kend = kh ? 9 : 4;

    int t = threadIdx.x;
    int lane = t & 31;
    int wrp = t >> 5;
    int wm = wrp >> 1, wn = wrp & 1;

    int4*   s_pq = (int4*)(sm + SM_PQ);
    float4* s_wq = (float4*)(sm + SM_WQ);

    const float*  omb_  = g_om + (size_t)b * JJ * HWT;
    const float4* imgf4 = (const float4*)(g_nhwc2 + (size_t)b * HWT * 128);

    int q = t & 15, px8 = t >> 4;
    int s_smp = q >> 1;
    int lnc = (q & 1) * 2;

    float d[2][4][4];
#pragma unroll
    for (int i = 0; i < 2; i++)
#pragma unroll
        for (int j = 0; j < 4; j++)
#pragma unroll
            for (int e = 0; e < 4; e++) d[i][j][e] = 0.f;

    for (int k = kstart; k < kend; k++) {
        if (k != kstart) __syncthreads();

        if (t < 128) {
            int gy = tY * 8 + (t >> 4), gx = tX * 16 + (t & 15);
            int p = gy * WW + gx;
            float dy = omb_[(2 * k) * HWT + p];
            float dx = omb_[(2 * k + 1) * HWT + p];
            float mv = omb_[(18 + k) * HWT + p];
            float m = 1.f / (1.f + __expf(-mv));
            float y = (float)(gy - 1 + k / 3) + dy;
            float x = (float)(gx - 1 + k % 3) + dx;
            float yf = floorf(y), xf = floorf(x);
            int yi = (int)yf, xi = (int)xf;
            float wy = y - yf, wx = x - xf;
            bool vy0 = (yi >= 0) && (yi < HH);
            bool vy1 = (yi >= -1) && (yi < HH - 1);
            bool vx0 = (xi >= 0) && (xi < WW);
            bool vx1 = (xi >= -1) && (xi < WW - 1);
            float w00 = (vy0 && vx0) ? (1.f - wy) * (1.f - wx) * m : 0.f;
            float w01 = (vy0 && vx1) ? (1.f - wy) * wx * m : 0.f;
            float w10 = (vy1 && vx0) ? wy * (1.f - wx) * m : 0.f;
            float w11 = (vy1 && vx1) ? wy * wx * m : 0.f;
            int y0c = min(max(yi, 0), HH - 1), y1c = min(max(yi + 1, 0), HH - 1);
            int x0c = min(max(xi, 0), WW - 1), x1c = min(max(xi + 1, 0), WW - 1);
            s_pq[t] = make_int4(y0c * WW + x0c, y0c * WW + x1c,
                                y1c * WW + x0c, y1c * WW + x1c);
            s_wq[t] = make_float4(w00, w01, w10, w11);
        }
        __syncthreads();

        // Sampling (coalesced over channels) + hi/lo split, fragment STS
#pragma unroll
        for (int j = 0; j < 8; j++) {
            int px = px8 * 8 + j;
            int4 pq = s_pq[px];
            float4 wq = s_wq[px];
            float a0 = 0.f, a1 = 0.f, a2 = 0.f, a3 = 0.f;
            float4 v;
            v = imgf4[pq.x * 32 + q];
            a0 = fmaf(wq.x, v.x, a0); a1 = fmaf(wq.x, v.y, a1);
            a2 = fmaf(wq.x, v.z, a2); a3 = fmaf(wq.x, v.w, a3);
            v = imgf4[pq.y * 32 + q];
            a0 = fmaf(wq.y, v.x, a0); a1 = fmaf(wq.y, v.y, a1);
            a2 = fmaf(wq.y, v.z, a2); a3 = fmaf(wq.y, v.w, a3);
            v = imgf4[pq.z * 32 + q];
            a0 = fmaf(wq.z, v.x, a0); a1 = fmaf(wq.z, v.y, a1);
            a2 = fmaf(wq.z, v.z, a2); a3 = fmaf(wq.z, v.w, a3);
            v = imgf4[pq.w * 32 + q];
            a0 = fmaf(wq.w, v.x, a0); a1 = fmaf(wq.w, v.y, a1);
            a2 = fmaf(wq.w, v.z, a2); a3 = fmaf(wq.w, v.w, a3);

            float h0 = tf32r(a0), h1 = tf32r(a1), h2 = tf32r(a2), h3 = tf32r(a3);
            float l0 = tf32r(a0 - h0), l1 = tf32r(a1 - h1);
            float l2 = tf32r(a2 - h2), l3 = tf32r(a3 - h3);

            int mt = px >> 4;
            int r = px & 7;
            int high = (px >> 3) & 1;
            int fo = (mt * 8 + s_smp) * 528 + high * 8;
            int la = (r * 4 + lnc) * 16;
            *(float2*)(sm + SM_AHI + fo + la)      = make_float2(h0, h1);
            *(float2*)(sm + SM_AHI + fo + la + 16) = make_float2(h2, h3);
            *(float2*)(sm + SM_ALO + fo + la)      = make_float2(l0, l1);
            *(float2*)(sm + SM_ALO + fo + la + 16) = make_float2(l2, l3);
        }
        __syncthreads();

        // GEMM: 3 passes (hh, lh, hl); B direct from gmem
        {
            const char* Ah = sm + SM_AHI;
            const char* Al = sm + SM_ALO;
            const uint2* Bg = (const uint2*)(g_wtB + (size_t)k * 4096);
#pragma unroll
            for (int s = 0; s < 8; s++) {
                int f0 = ((wm * 2 + 0) * 8 + s) * 528 + lane * 16;
                int f1 = ((wm * 2 + 1) * 8 + s) * 528 + lane * 16;
                uint4 ah0 = *(const uint4*)(Ah + f0);
                uint4 ah1 = *(const uint4*)(Ah + f1);
                uint4 al0 = *(const uint4*)(Al + f0);
                uint4 al1 = *(const uint4*)(Al + f1);
#pragma unroll
                for (int nt = 0; nt < 4; nt++) {
                    int fidx = (s * 8 + wn * 4 + nt) * 32 + lane;
                    uint2 bh = __ldg(&Bg[fidx]);
                    uint2 bl = __ldg(&Bg[fidx + 2048]);
                    MMA8(d[0][nt], ah0.x, ah0.z, ah0.y, ah0.w, bh.x, bh.y);
                    MMA8(d[0][nt], al0.x, al0.z, al0.y, al0.w, bh.x, bh.y);
                    MMA8(d[0][nt], ah0.x, ah0.z, ah0.y, ah0.w, bl.x, bl.y);
                    MMA8(d[1][nt], ah1.x, ah1.z, ah1.y, ah1.w, bh.x, bh.y);
                    MMA8(d[1][nt], al1.x, al1.z, al1.y, al1.w, bh.x, bh.y);
                    MMA8(d[1][nt], ah1.x, ah1.z, ah1.y, ah1.w, bl.x, bl.y);
                }
            }
        }
    }

    // Epilogue: write partials
#pragma unroll
    for (int mi = 0; mi < 2; mi++) {
        int pxb = (wm * 2 + mi) * 16 + (lane >> 2);
        int gy0 = tY * 8 + (pxb >> 4), gx0 = tX * 16 + (pxb & 15);
        int px2 = pxb + 8;
        int gy1 = tY * 8 + (px2 >> 4), gx1 = tX * 16 + (px2 & 15);
#pragma unroll
        for (int nt = 0; nt < 4; nt++) {
            int o = wn * 32 + nt * 8 + (lane & 3) * 2;
            size_t base = (((size_t)kh * BB + b) * OO + o) * HWT;
            g_outp[base + gy0 * WW + gx0]       = d[mi][nt][0];
            g_outp[base + HWT + gy0 * WW + gx0] = d[mi][nt][1];
            g_outp[base + gy1 * WW + gx1]       = d[mi][nt][2];
            g_outp[base + HWT + gy1 * WW + gx1] = d[mi][nt][3];
        }
    }
}

// ---------------------------------------------------------------------------
// Kernel 4b: out = g_outp[0] + g_outp[1]
// ---------------------------------------------------------------------------
__global__ __launch_bounds__(256) void reduce_out(float* __restrict__ out) {
    int i = blockIdx.x * 256 + threadIdx.x;
    if (i >= BB * OO * 1024) return;
    float4 a = ((const float4*)g_outp)[i];
    float4 c = ((const float4*)g_outp)[i + BB * OO * 1024];
    ((float4*)out)[i] = make_float4(a.x + c.x, a.y + c.y, a.z + c.z, a.w + c.w);
}

// ---------------------------------------------------------------------------
extern "C" void kernel_launch(void* const* d_in, const int* in_sizes, int n_in,
                              void* d_out, int out_size) {
    const float* input_feat = (const float*)d_in[0];
    const float* degrad     = (const float*)d_in[1];
    const float* weight     = (const float*)d_in[2];
    const float* om_weight  = (const float*)d_in[3];
    const float* om_bias    = (const float*)d_in[4];
    float* out = (float*)d_out;

    cudaFuncSetAttribute(om_gemm, cudaFuncAttributeMaxDynamicSharedMemorySize, OM_TOT);
    cudaFuncSetAttribute(deform, cudaFuncAttributeMaxDynamicSharedMemorySize, SM_TOT);

    transpose_nhwc2<<<BB * HH, 256>>>(input_feat, degrad);
    transpose_w<<<(9 * 2 * 2048 + 255) / 256, 256>>>(weight);
    transpose_omw<<<(9*2*8*4*32 + 255) / 256, 256>>>(om_weight);
    om_gemm<<<dim3(BB * 32, 2), 256, OM_TOT>>>();
    reduce_om2<<<(BB * JJ * 1024 + 255) / 256, 256>>>(om_bias);
    deform<<<dim3(BB * 32, 2), 256, SM_TOT>>>();
    reduce_out<<<(BB * OO * 1024 + 255) / 256, 256>>>(out);
}

// round 13
// speedup vs baseline: 1.0577x; 1.0577x over previous
#include <cuda_runtime.h>
#include <cstdint>

#define BB 8
#define CC 64
#define HH 64
#define WW 64
#define OO 64
#define HWT (HH*WW)
#define JJ 27

// tf32 round (keeps top 10 mantissa bits)
__device__ __forceinline__ float tf32r(float x) {
    unsigned u;
    asm("cvt.rna.tf32.f32 %0, %1;" : "=r"(u) : "f"(x));
    return __uint_as_float(u);
}

// mma.sync m16n8k8 tf32: D += A*B (fp32 accum)
#define MMA8(D, A0, A1, A2, A3, B0, B1)                                   \
    asm volatile("mma.sync.aligned.m16n8k8.row.col.f32.tf32.tf32.f32 "     \
        "{%0,%1,%2,%3}, {%4,%5,%6,%7}, {%8,%9}, {%0,%1,%2,%3};"            \
        : "+f"((D)[0]), "+f"((D)[1]), "+f"((D)[2]), "+f"((D)[3])           \
        : "r"(A0), "r"(A1), "r"(A2), "r"(A3), "r"(B0), "r"(B1))

// Scratch (device globals: no allocation allowed)
__device__ float  g_nhwc2[BB*HH*WW*128];   // concat(feat, degrad) NHWC, 128 ch
__device__ float  g_om[BB*JJ*HWT];         // offset/mask conv output
__device__ __align__(16) float2 g_wtB[9*2*2048];    // deform weights hi/lo B-frags (perm layout)
__device__ __align__(16) float2 g_omB[9*16*4*32];   // om weights B-frags, natural (b0=c, b1=c+4)

// ---------------------------------------------------------------------------
// Kernel 1: NCHW feat+degrad -> g_nhwc2[b][y][x][128]. One block per (b,h).
// ---------------------------------------------------------------------------
__global__ __launch_bounds__(256) void transpose_nhwc2(const float* __restrict__ feat,
                                                       const float* __restrict__ deg) {
    int bh = blockIdx.x;
    int b = bh / HH, h = bh % HH;
    __shared__ float tile[128][WW + 1];
    for (int i = threadIdx.x; i < 128 * WW; i += 256) {
        int c = i >> 6, w = i & 63;
        const float* src = (c < 64) ? feat : deg;
        tile[c][w] = src[(((size_t)b * 64 + (c & 63)) * HH + h) * WW + w];
    }
    __syncthreads();
    float* dst = g_nhwc2 + (((size_t)b * HH + h) * WW) * 128;
    for (int i = threadIdx.x; i < 128 * WW; i += 256) {
        int w = i >> 7, c = i & 127;
        dst[w * 128 + c] = tile[c][w];
    }
}

// ---------------------------------------------------------------------------
// Kernel 2a: deform weight (O,C,3,3) -> g_wtB (perm B-frag layout, hi/lo).
// ---------------------------------------------------------------------------
__global__ void transpose_w(const float* __restrict__ w) {
    int i = blockIdx.x * blockDim.x + threadIdx.x;
    if (i >= 9*2*2048) return;
    int k = i / 4096;
    int r = i % 4096;
    int h = r >> 11;
    int e = r & 2047;
    int lane = e & 31;
    int frag = e >> 5;
    int nt = frag & 7, s = frag >> 3;
    int o = nt*8 + (lane >> 2);
    int c0 = s*8 + (lane & 3)*2;
    float v0 = w[(o*CC + c0)*9 + k];
    float v1 = w[(o*CC + c0 + 1)*9 + k];
    float h0 = tf32r(v0), h1 = tf32r(v1);
    g_wtB[i] = h ? make_float2(tf32r(v0 - h0), tf32r(v1 - h1))
                 : make_float2(h0, h1);
}

// ---------------------------------------------------------------------------
// Kernel 2b: om_weight (27,128,3,3) -> g_omB, natural order:
// b0 = ch (s*8 + lane%4), b1 = ch+4; n = nt*8 + lane/4 (j, padded to 32).
// Index: ((k*16 + s)*4 + nt)*32 + lane
// ---------------------------------------------------------------------------
__global__ void transpose_omw(const float* __restrict__ omw) {
    int i = blockIdx.x * blockDim.x + threadIdx.x;
    if (i >= 9*16*4*32) return;
    int lane = i & 31;
    int r = i >> 5;
    int nt = r & 3;  r >>= 2;
    int s = r & 15;
    int k = r >> 4;
    int j = nt*8 + (lane >> 2);
    int c = s*8 + (lane & 3);
    float v0 = 0.f, v1 = 0.f;
    if (j < JJ) {
        v0 = omw[(j*128 + c)*9 + k];
        v1 = omw[(j*128 + c + 4)*9 + k];
    }
    g_omB[i] = make_float2(tf32r(v0), tf32r(v1));
}

// ---------------------------------------------------------------------------
// Kernel 3: om conv, stationary-halo tf32 GEMM.
// Block = (b, 8x16 px tile): halo 10x18x128ch in smem (swizzled, tf32-rounded),
// per tap A fragments = address offsets (4 conflict-free LDS.32).
// Warp = 1 M-tile x 4 N-tiles. Direct g_om + bias write.
// ---------------------------------------------------------------------------
#define OMH_TOT (10*18*128*4)   // 92160 bytes

__global__ __launch_bounds__(256) void om_gemm(const float* __restrict__ omb) {
    extern __shared__ float sh[];
    int bi = blockIdx.x;
    int b  = bi >> 5;
    int tY = (bi >> 2) & 7;
    int tX = bi & 3;

    int t = threadIdx.x;
    int lane = t & 31;
    int mt = t >> 5;              // warp = M-tile (image row py)
    int g = lane >> 2, tg = lane & 3;

    const float4* img = (const float4*)(g_nhwc2 + (size_t)b * HWT * 128);

    // Halo load: 10 x 18 px, 128 ch, swizzle c' = c ^ ((hx&7)<<2), tf32-rounded
    for (int i = t; i < 10*18*32; i += 256) {
        int q  = i & 31;
        int hx = (i >> 5) % 18;
        int hy = i / (18*32);
        int gy = tY*8 + hy - 1, gx = tX*16 + hx - 1;
        float4 v = make_float4(0.f, 0.f, 0.f, 0.f);
        if (gy >= 0 && gy < HH && gx >= 0 && gx < WW)
            v = img[(gy*WW + gx)*32 + q];
        v.x = tf32r(v.x); v.y = tf32r(v.y); v.z = tf32r(v.z); v.w = tf32r(v.w);
        int c = (q*4) ^ ((hx & 7) << 2);
        *(float4*)&sh[(hy*18 + hx)*128 + c] = v;
    }
    __syncthreads();

    float d[4][4];
#pragma unroll
    for (int n = 0; n < 4; n++)
#pragma unroll
        for (int e = 0; e < 4; e++) d[n][e] = 0.f;

    for (int k = 0; k < 9; k++) {
        int ky = k/3 - 1, kx = k%3 - 1;
        int hy = mt + 1 + ky;
        int hx = g + 1 + kx;            // a0/a2 column (px16 = g)
        int sw = (hx & 7) << 2;
        const float* arow = sh + (hy*18 + hx)*128;   // a1/a3 at +8*128 (same sw)
        const uint2* Bg = (const uint2*)(g_omB + (size_t)k * 2048);
#pragma unroll
        for (int s = 0; s < 16; s++) {
            int cb = s*8 + tg;
            int c0 = cb ^ sw;
            int c4 = (cb + 4) ^ sw;       // [R12 bug: was c0+4 — wrong & OOB]
            uint32_t a0 = __float_as_uint(arow[c0]);
            uint32_t a2 = __float_as_uint(arow[c4]);
            uint32_t a1 = __float_as_uint(arow[1024 + c0]);
            uint32_t a3 = __float_as_uint(arow[1024 + c4]);
#pragma unroll
            for (int nt = 0; nt < 4; nt++) {
                uint2 bh = __ldg(&Bg[(s*4 + nt)*32 + lane]);
                MMA8(d[nt], a0, a1, a2, a3, bh.x, bh.y);
            }
        }
    }

    // Epilogue: D rows = px16 (g, g+8), cols j = nt*8 + 2*tg (+1)
    {
        int gy = tY*8 + mt;
        int gx0 = tX*16 + g;
#pragma unroll
        for (int nt = 0; nt < 4; nt++) {
            int j = nt*8 + tg*2;
            size_t base = ((size_t)b * JJ + j) * HWT + gy * WW + gx0;
            if (j < JJ) {
                float bj = omb[j];
                g_om[base]     = d[nt][0] + bj;
                g_om[base + 8] = d[nt][2] + bj;
            }
            if (j + 1 < JJ) {
                float bj = omb[j + 1];
                g_om[base + HWT]     = d[nt][1] + bj;
                g_om[base + HWT + 8] = d[nt][3] + bj;
            }
        }
    }
}

// ---------------------------------------------------------------------------
// Kernel 4: deformable conv, 3-pass tf32, spatial split: 8x8 px tiles (512
// blocks), warp = 1 M-tile x 4 N-tiles, B from gmem, direct out writes.
// ---------------------------------------------------------------------------
#define SM_PQ  0
#define SM_WQ  1024
#define SM_AHI 2048
#define SM_ALO (SM_AHI + 4*8*528)
#define SM_TOT (SM_ALO + 4*8*528)

__global__ __launch_bounds__(256, 4) void deform(float* __restrict__ out) {
    extern __shared__ char sm[];
    int bi = blockIdx.x;            // 512 blocks: b(8) x tY(8) x tX(8)
    int b  = bi >> 6;
    int tY = (bi >> 3) & 7;
    int tX = bi & 7;

    int t = threadIdx.x;
    int lane = t & 31;
    int wrp = t >> 5;
    int wm = wrp >> 1, wn = wrp & 1;

    int4*   s_pq = (int4*)(sm + SM_PQ);
    float4* s_wq = (float4*)(sm + SM_WQ);

    const float*  omb_  = g_om + (size_t)b * JJ * HWT;
    const float4* imgf4 = (const float4*)(g_nhwc2 + (size_t)b * HWT * 128);

    int q = t & 15, pxs = t >> 4;   // sampler: 4-ch group q, px slot (4 px each)
    int s_smp = q >> 1;
    int lnc = (q & 1) * 2;

    float d[4][4];
#pragma unroll
    for (int n = 0; n < 4; n++)
#pragma unroll
        for (int e = 0; e < 4; e++) d[n][e] = 0.f;

    for (int k = 0; k < 9; k++) {
        if (k) __syncthreads();

        // Stage A: per-pixel bilinear metadata (64 px)
        if (t < 64) {
            int gy = tY*8 + (t >> 3), gx = tX*8 + (t & 7);
            int p = gy * WW + gx;
            float dy = omb_[(2 * k) * HWT + p];
            float dx = omb_[(2 * k + 1) * HWT + p];
            float mv = omb_[(18 + k) * HWT + p];
            float m = 1.f / (1.f + __expf(-mv));
            float y = (float)(gy - 1 + k / 3) + dy;
            float x = (float)(gx - 1 + k % 3) + dx;
            float yf = floorf(y), xf = floorf(x);
            int yi = (int)yf, xi = (int)xf;
            float wy = y - yf, wx = x - xf;
            bool vy0 = (yi >= 0) && (yi < HH);
            bool vy1 = (yi >= -1) && (yi < HH - 1);
            bool vx0 = (xi >= 0) && (xi < WW);
            bool vx1 = (xi >= -1) && (xi < WW - 1);
            float w00 = (vy0 && vx0) ? (1.f - wy) * (1.f - wx) * m : 0.f;
            float w01 = (vy0 && vx1) ? (1.f - wy) * wx * m : 0.f;
            float w10 = (vy1 && vx0) ? wy * (1.f - wx) * m : 0.f;
            float w11 = (vy1 && vx1) ? wy * wx * m : 0.f;
            int y0c = min(max(yi, 0), HH - 1), y1c = min(max(yi + 1, 0), HH - 1);
            int x0c = min(max(xi, 0), WW - 1), x1c = min(max(xi + 1, 0), WW - 1);
            s_pq[t] = make_int4(y0c * WW + x0c, y0c * WW + x1c,
                                y1c * WW + x0c, y1c * WW + x1c);
            s_wq[t] = make_float4(w00, w01, w10, w11);
        }
        __syncthreads();

        // Stage B: sampling (coalesced over channels) + hi/lo split, frag STS
#pragma unroll
        for (int j = 0; j < 4; j++) {
            int px = pxs * 4 + j;
            int4 pq = s_pq[px];
            float4 wq = s_wq[px];
            float a0 = 0.f, a1 = 0.f, a2 = 0.f, a3 = 0.f;
            float4 v;
            v = imgf4[pq.x * 32 + q];
            a0 = fmaf(wq.x, v.x, a0); a1 = fmaf(wq.x, v.y, a1);
            a2 = fmaf(wq.x, v.z, a2); a3 = fmaf(wq.x, v.w, a3);
            v = imgf4[pq.y * 32 + q];
            a0 = fmaf(wq.y, v.x, a0); a1 = fmaf(wq.y, v.y, a1);
            a2 = fmaf(wq.y, v.z, a2); a3 = fmaf(wq.y, v.w, a3);
            v = imgf4[pq.z * 32 + q];
            a0 = fmaf(wq.z, v.x, a0); a1 = fmaf(wq.z, v.y, a1);
            a2 = fmaf(wq.z, v.z, a2); a3 = fmaf(wq.z, v.w, a3);
            v = imgf4[pq.w * 32 + q];
            a0 = fmaf(wq.w, v.x, a0); a1 = fmaf(wq.w, v.y, a1);
            a2 = fmaf(wq.w, v.z, a2); a3 = fmaf(wq.w, v.w, a3);

            float h0 = tf32r(a0), h1 = tf32r(a1), h2 = tf32r(a2), h3 = tf32r(a3);
            float l0 = tf32r(a0 - h0), l1 = tf32r(a1 - h1);
            float l2 = tf32r(a2 - h2), l3 = tf32r(a3 - h3);

            int mt = px >> 4;
            int r = px & 7;
            int high = (px >> 3) & 1;
            int fo = (mt * 8 + s_smp) * 528 + high * 8;
            int la = (r * 4 + lnc) * 16;
            *(float2*)(sm + SM_AHI + fo + la)      = make_float2(h0, h1);
            *(float2*)(sm + SM_AHI + fo + la + 16) = make_float2(h2, h3);
            *(float2*)(sm + SM_ALO + fo + la)      = make_float2(l0, l1);
            *(float2*)(sm + SM_ALO + fo + la + 16) = make_float2(l2, l3);
        }
        __syncthreads();

        // Stage C: 3-pass GEMM (hh, lh, hl), B direct from gmem
        {
            const char* Ah = sm + SM_AHI;
            const char* Al = sm + SM_ALO;
            const uint2* Bg = (const uint2*)(g_wtB + (size_t)k * 4096);
#pragma unroll
            for (int s = 0; s < 8; s++) {
                int f0 = (wm * 8 + s) * 528 + lane * 16;
                uint4 ah = *(const uint4*)(Ah + f0);
                uint4 al = *(const uint4*)(Al + f0);
#pragma unroll
                for (int nt = 0; nt < 4; nt++) {
                    int fidx = (s * 8 + wn * 4 + nt) * 32 + lane;
                    uint2 bh = __ldg(&Bg[fidx]);
                    uint2 bl = __ldg(&Bg[fidx + 2048]);
                    MMA8(d[nt], ah.x, ah.z, ah.y, ah.w, bh.x, bh.y);
                    MMA8(d[nt], al.x, al.z, al.y, al.w, bh.x, bh.y);
                    MMA8(d[nt], ah.x, ah.z, ah.y, ah.w, bl.x, bl.y);
                }
            }
        }
    }

    // Epilogue: direct out writes (B,O,H,W)
    {
        int pxb = wm * 16 + (lane >> 2);
        int gy0 = tY * 8 + (pxb >> 3), gx0 = tX * 8 + (pxb & 7);
#pragma unroll
        for (int nt = 0; nt < 4; nt++) {
            int o = wn * 32 + nt * 8 + (lane & 3) * 2;
            size_t base = ((size_t)b * OO + o) * HWT;
            out[base + gy0 * WW + gx0]             = d[nt][0];
            out[base + HWT + gy0 * WW + gx0]       = d[nt][1];
            out[base + (gy0 + 1) * WW + gx0]       = d[nt][2];
            out[base + HWT + (gy0 + 1) * WW + gx0] = d[nt][3];
        }
    }
}

// ---------------------------------------------------------------------------
extern "C" void kernel_launch(void* const* d_in, const int* in_sizes, int n_in,
                              void* d_out, int out_size) {
    const float* input_feat = (const float*)d_in[0];
    const float* degrad     = (const float*)d_in[1];
    const float* weight     = (const float*)d_in[2];
    const float* om_weight  = (const float*)d_in[3];
    const float* om_bias    = (const float*)d_in[4];
    float* out = (float*)d_out;

    cudaFuncSetAttribute(om_gemm, cudaFuncAttributeMaxDynamicSharedMemorySize, OMH_TOT);
    cudaFuncSetAttribute(deform, cudaFuncAttributeMaxDynamicSharedMemorySize, SM_TOT);

    transpose_nhwc2<<<BB * HH, 256>>>(input_feat, degrad);
    transpose_w<<<(9 * 2 * 2048 + 255) / 256, 256>>>(weight);
    transpose_omw<<<(9*16*4*32 + 255) / 256, 256>>>(om_weight);
    om_gemm<<<BB * 32, 256, OMH_TOT>>>(om_bias);
    deform<<<BB * 64, 256, SM_TOT>>>(out);
}

// round 14
// speedup vs baseline: 1.1474x; 1.0847x over previous
#include <cuda_runtime.h>
#include <cstdint>

#define BB 8
#define CC 64
#define HH 64
#define WW 64
#define OO 64
#define HWT (HH*WW)
#define JJ 27

// tf32 round (keeps top 10 mantissa bits)
__device__ __forceinline__ float tf32r(float x) {
    unsigned u;
    asm("cvt.rna.tf32.f32 %0, %1;" : "=r"(u) : "f"(x));
    return __uint_as_float(u);
}

// mma.sync m16n8k8 tf32: D += A*B (fp32 accum)
#define MMA8(D, A0, A1, A2, A3, B0, B1)                                   \
    asm volatile("mma.sync.aligned.m16n8k8.row.col.f32.tf32.tf32.f32 "     \
        "{%0,%1,%2,%3}, {%4,%5,%6,%7}, {%8,%9}, {%0,%1,%2,%3};"            \
        : "+f"((D)[0]), "+f"((D)[1]), "+f"((D)[2]), "+f"((D)[3])           \
        : "r"(A0), "r"(A1), "r"(A2), "r"(A3), "r"(B0), "r"(B1))

// Scratch (device globals: no allocation allowed)
__device__ float  g_nhwc2[BB*HH*WW*128];   // concat(feat, degrad) NHWC, 128 ch
__device__ float  g_om[BB*JJ*HWT];         // offset/mask conv output
__device__ __align__(16) float2 g_wtB[9*2*2048];    // deform weights hi/lo B-frags (perm layout)
__device__ __align__(16) float2 g_omB[9*16*4*32];   // om weights B-frags, natural (b0=c, b1=c+4)

// ---------------------------------------------------------------------------
// Kernel 1: NCHW feat+degrad -> g_nhwc2[b][y][x][128]. One block per (b,h).
// ---------------------------------------------------------------------------
__global__ __launch_bounds__(256) void transpose_nhwc2(const float* __restrict__ feat,
                                                       const float* __restrict__ deg) {
    int bh = blockIdx.x;
    int b = bh / HH, h = bh % HH;
    __shared__ float tile[128][WW + 1];
    for (int i = threadIdx.x; i < 128 * WW; i += 256) {
        int c = i >> 6, w = i & 63;
        const float* src = (c < 64) ? feat : deg;
        tile[c][w] = src[(((size_t)b * 64 + (c & 63)) * HH + h) * WW + w];
    }
    __syncthreads();
    float* dst = g_nhwc2 + (((size_t)b * HH + h) * WW) * 128;
    for (int i = threadIdx.x; i < 128 * WW; i += 256) {
        int w = i >> 7, c = i & 127;
        dst[w * 128 + c] = tile[c][w];
    }
}

// ---------------------------------------------------------------------------
// Kernel 2a: deform weight (O,C,3,3) -> g_wtB (perm B-frag layout, hi/lo).
// ---------------------------------------------------------------------------
__global__ void transpose_w(const float* __restrict__ w) {
    int i = blockIdx.x * blockDim.x + threadIdx.x;
    if (i >= 9*2*2048) return;
    int k = i / 4096;
    int r = i % 4096;
    int h = r >> 11;
    int e = r & 2047;
    int lane = e & 31;
    int frag = e >> 5;
    int nt = frag & 7, s = frag >> 3;
    int o = nt*8 + (lane >> 2);
    int c0 = s*8 + (lane & 3)*2;
    float v0 = w[(o*CC + c0)*9 + k];
    float v1 = w[(o*CC + c0 + 1)*9 + k];
    float h0 = tf32r(v0), h1 = tf32r(v1);
    g_wtB[i] = h ? make_float2(tf32r(v0 - h0), tf32r(v1 - h1))
                 : make_float2(h0, h1);
}

// ---------------------------------------------------------------------------
// Kernel 2b: om_weight (27,128,3,3) -> g_omB, natural order:
// b0 = ch (s*8 + lane%4), b1 = ch+4; n = nt*8 + lane/4 (j, padded to 32).
// Index: ((k*16 + s)*4 + nt)*32 + lane
// ---------------------------------------------------------------------------
__global__ void transpose_omw(const float* __restrict__ omw) {
    int i = blockIdx.x * blockDim.x + threadIdx.x;
    if (i >= 9*16*4*32) return;
    int lane = i & 31;
    int r = i >> 5;
    int nt = r & 3;  r >>= 2;
    int s = r & 15;
    int k = r >> 4;
    int j = nt*8 + (lane >> 2);
    int c = s*8 + (lane & 3);
    float v0 = 0.f, v1 = 0.f;
    if (j < JJ) {
        v0 = omw[(j*128 + c)*9 + k];
        v1 = omw[(j*128 + c + 4)*9 + k];
    }
    g_omB[i] = make_float2(tf32r(v0), tf32r(v1));
}

// ---------------------------------------------------------------------------
// Kernel 3: om conv, stationary-halo tf32 GEMM, 8x8 px tiles + 64-ch chunks.
// Block = (b, 8x8 px tile): halo 10x10x64ch in smem (25.6KB, swizzled),
// 2 channel passes, D in registers across passes. 512 blocks.
// Warp = 1 M-tile (16px) x 2 N-tiles (j 16). Direct g_om + bias write.
// ---------------------------------------------------------------------------
#define OMH_TOT (10*10*64*4)   // 25600 bytes

__global__ __launch_bounds__(256, 4) void om_gemm(const float* __restrict__ omb) {
    extern __shared__ float sh[];
    int bi = blockIdx.x;            // 512 blocks: b(8) x tY(8) x tX(8)
    int b  = bi >> 6;
    int tY = (bi >> 3) & 7;
    int tX = bi & 7;

    int t = threadIdx.x;
    int lane = t & 31;
    int wrp = t >> 5;
    int wm = wrp >> 1, wn = wrp & 1;   // 4 M-tiles x 2 N-halves
    int g = lane >> 2, tg = lane & 3;

    const float4* img = (const float4*)(g_nhwc2 + (size_t)b * HWT * 128);

    float d[2][4];
#pragma unroll
    for (int n = 0; n < 2; n++)
#pragma unroll
        for (int e = 0; e < 4; e++) d[n][e] = 0.f;

#pragma unroll
    for (int cc = 0; cc < 2; cc++) {
        if (cc) __syncthreads();
        // Halo load: 10x10 px, 64 ch chunk, swizzle c' = c ^ ((hx&7)<<2)
        for (int i = t; i < 10*10*16; i += 256) {
            int q  = i & 15;
            int hx = (i >> 4) % 10;
            int hy = i / 160;
            int gy = tY*8 + hy - 1, gx = tX*8 + hx - 1;
            float4 v = make_float4(0.f, 0.f, 0.f, 0.f);
            if (gy >= 0 && gy < HH && gx >= 0 && gx < WW)
                v = img[(gy*WW + gx)*32 + cc*16 + q];
            v.x = tf32r(v.x); v.y = tf32r(v.y); v.z = tf32r(v.z); v.w = tf32r(v.w);
            int c = (q*4) ^ ((hx & 7) << 2);
            *(float4*)&sh[(hy*10 + hx)*64 + c] = v;
        }
        __syncthreads();

        for (int k = 0; k < 9; k++) {
            int ky = k/3 - 1, kx = k%3 - 1;
            int hy = wm*2 + 1 + ky;
            int hx = g + 1 + kx;
            int sw = (hx & 7) << 2;
            const float* arow = sh + (hy*10 + hx)*64;   // a1/a3 at +640 (next row)
            const uint2* Bg = (const uint2*)(g_omB + (size_t)k * 2048);
#pragma unroll
            for (int s = 0; s < 8; s++) {
                int cb = s*8 + tg;
                int c0 = cb ^ sw;
                int c4 = (cb + 4) ^ sw;
                uint32_t a0 = __float_as_uint(arow[c0]);
                uint32_t a2 = __float_as_uint(arow[c4]);
                uint32_t a1 = __float_as_uint(arow[640 + c0]);
                uint32_t a3 = __float_as_uint(arow[640 + c4]);
                int sg = cc*8 + s;
#pragma unroll
                for (int nt = 0; nt < 2; nt++) {
                    uint2 bh = __ldg(&Bg[(sg*4 + wn*2 + nt)*32 + lane]);
                    MMA8(d[nt], a0, a1, a2, a3, bh.x, bh.y);
                }
            }
        }
    }

    // Epilogue: rows = px wm*16+g (gy) and +8 (gy+1), cols j = (wn*2+nt)*8+2tg
    {
        int gy = tY*8 + wm*2;
        int gx = tX*8 + g;
#pragma unroll
        for (int nt = 0; nt < 2; nt++) {
            int j = (wn*2 + nt)*8 + tg*2;
            size_t base = ((size_t)b * JJ + j) * HWT + gy * WW + gx;
            if (j < JJ) {
                float bj = omb[j];
                g_om[base]      = d[nt][0] + bj;
                g_om[base + WW] = d[nt][2] + bj;
            }
            if (j + 1 < JJ) {
                float bj = omb[j + 1];
                g_om[base + HWT]      = d[nt][1] + bj;
                g_om[base + HWT + WW] = d[nt][3] + bj;
            }
        }
    }
}

// ---------------------------------------------------------------------------
// Kernel 4: deformable conv, 3-pass tf32, 8x8 px tiles (unchanged from R13).
// ---------------------------------------------------------------------------
#define SM_PQ  0
#define SM_WQ  1024
#define SM_AHI 2048
#define SM_ALO (SM_AHI + 4*8*528)
#define SM_TOT (SM_ALO + 4*8*528)

__global__ __launch_bounds__(256, 4) void deform(float* __restrict__ out) {
    extern __shared__ char sm[];
    int bi = blockIdx.x;            // 512 blocks: b(8) x tY(8) x tX(8)
    int b  = bi >> 6;
    int tY = (bi >> 3) & 7;
    int tX = bi & 7;

    int t = threadIdx.x;
    int lane = t & 31;
    int wrp = t >> 5;
    int wm = wrp >> 1, wn = wrp & 1;

    int4*   s_pq = (int4*)(sm + SM_PQ);
    float4* s_wq = (float4*)(sm + SM_WQ);

    const float*  omb_  = g_om + (size_t)b * JJ * HWT;
    const float4* imgf4 = (const float4*)(g_nhwc2 + (size_t)b * HWT * 128);

    int q = t & 15, pxs = t >> 4;
    int s_smp = q >> 1;
    int lnc = (q & 1) * 2;

    float d[4][4];
#pragma unroll
    for (int n = 0; n < 4; n++)
#pragma unroll
        for (int e = 0; e < 4; e++) d[n][e] = 0.f;

    for (int k = 0; k < 9; k++) {
        if (k) __syncthreads();

        if (t < 64) {
            int gy = tY*8 + (t >> 3), gx = tX*8 + (t & 7);
            int p = gy * WW + gx;
            float dy = omb_[(2 * k) * HWT + p];
            float dx = omb_[(2 * k + 1) * HWT + p];
            float mv = omb_[(18 + k) * HWT + p];
            float m = 1.f / (1.f + __expf(-mv));
            float y = (float)(gy - 1 + k / 3) + dy;
            float x = (float)(gx - 1 + k % 3) + dx;
            float yf = floorf(y), xf = floorf(x);
            int yi = (int)yf, xi = (int)xf;
            float wy = y - yf, wx = x - xf;
            bool vy0 = (yi >= 0) && (yi < HH);
            bool vy1 = (yi >= -1) && (yi < HH - 1);
            bool vx0 = (xi >= 0) && (xi < WW);
            bool vx1 = (xi >= -1) && (xi < WW - 1);
            float w00 = (vy0 && vx0) ? (1.f - wy) * (1.f - wx) * m : 0.f;
            float w01 = (vy0 && vx1) ? (1.f - wy) * wx * m : 0.f;
            float w10 = (vy1 && vx0) ? wy * (1.f - wx) * m : 0.f;
            float w11 = (vy1 && vx1) ? wy * wx * m : 0.f;
            int y0c = min(max(yi, 0), HH - 1), y1c = min(max(yi + 1, 0), HH - 1);
            int x0c = min(max(xi, 0), WW - 1), x1c = min(max(xi + 1, 0), WW - 1);
            s_pq[t] = make_int4(y0c * WW + x0c, y0c * WW + x1c,
                                y1c * WW + x0c, y1c * WW + x1c);
            s_wq[t] = make_float4(w00, w01, w10, w11);
        }
        __syncthreads();

#pragma unroll
        for (int j = 0; j < 4; j++) {
            int px = pxs * 4 + j;
            int4 pq = s_pq[px];
            float4 wq = s_wq[px];
            float a0 = 0.f, a1 = 0.f, a2 = 0.f, a3 = 0.f;
            float4 v;
            v = imgf4[pq.x * 32 + q];
            a0 = fmaf(wq.x, v.x, a0); a1 = fmaf(wq.x, v.y, a1);
            a2 = fmaf(wq.x, v.z, a2); a3 = fmaf(wq.x, v.w, a3);
            v = imgf4[pq.y * 32 + q];
            a0 = fmaf(wq.y, v.x, a0); a1 = fmaf(wq.y, v.y, a1);
            a2 = fmaf(wq.y, v.z, a2); a3 = fmaf(wq.y, v.w, a3);
            v = imgf4[pq.z * 32 + q];
            a0 = fmaf(wq.z, v.x, a0); a1 = fmaf(wq.z, v.y, a1);
            a2 = fmaf(wq.z, v.z, a2); a3 = fmaf(wq.z, v.w, a3);
            v = imgf4[pq.w * 32 + q];
            a0 = fmaf(wq.w, v.x, a0); a1 = fmaf(wq.w, v.y, a1);
            a2 = fmaf(wq.w, v.z, a2); a3 = fmaf(wq.w, v.w, a3);

            float h0 = tf32r(a0), h1 = tf32r(a1), h2 = tf32r(a2), h3 = tf32r(a3);
            float l0 = tf32r(a0 - h0), l1 = tf32r(a1 - h1);
            float l2 = tf32r(a2 - h2), l3 = tf32r(a3 - h3);

            int mt = px >> 4;
            int r = px & 7;
            int high = (px >> 3) & 1;
            int fo = (mt * 8 + s_smp) * 528 + high * 8;
            int la = (r * 4 + lnc) * 16;
            *(float2*)(sm + SM_AHI + fo + la)      = make_float2(h0, h1);
            *(float2*)(sm + SM_AHI + fo + la + 16) = make_float2(h2, h3);
            *(float2*)(sm + SM_ALO + fo + la)      = make_float2(l0, l1);
            *(float2*)(sm + SM_ALO + fo + la + 16) = make_float2(l2, l3);
        }
        __syncthreads();

        {
            const char* Ah = sm + SM_AHI;
            const char* Al = sm + SM_ALO;
            const uint2* Bg = (const uint2*)(g_wtB + (size_t)k * 4096);
#pragma unroll
            for (int s = 0; s < 8; s++) {
                int f0 = (wm * 8 + s) * 528 + lane * 16;
                uint4 ah = *(const uint4*)(Ah + f0);
                uint4 al = *(const uint4*)(Al + f0);
#pragma unroll
                for (int nt = 0; nt < 4; nt++) {
                    int fidx = (s * 8 + wn * 4 + nt) * 32 + lane;
                    uint2 bh = __ldg(&Bg[fidx]);
                    uint2 bl = __ldg(&Bg[fidx + 2048]);
                    MMA8(d[nt], ah.x, ah.z, ah.y, ah.w, bh.x, bh.y);
                    MMA8(d[nt], al.x, al.z, al.y, al.w, bh.x, bh.y);
                    MMA8(d[nt], ah.x, ah.z, ah.y, ah.w, bl.x, bl.y);
                }
            }
        }
    }

    {
        int pxb = wm * 16 + (lane >> 2);
        int gy0 = tY * 8 + (pxb >> 3), gx0 = tX * 8 + (pxb & 7);
#pragma unroll
        for (int nt = 0; nt < 4; nt++) {
            int o = wn * 32 + nt * 8 + (lane & 3) * 2;
            size_t base = ((size_t)b * OO + o) * HWT;
            out[base + gy0 * WW + gx0]             = d[nt][0];
            out[base + HWT + gy0 * WW + gx0]       = d[nt][1];
            out[base + (gy0 + 1) * WW + gx0]       = d[nt][2];
            out[base + HWT + (gy0 + 1) * WW + gx0] = d[nt][3];
        }
    }
}

// ---------------------------------------------------------------------------
extern "C" void kernel_launch(void* const* d_in, const int* in_sizes, int n_in,
                              void* d_out, int out_size) {
    const float* input_feat = (const float*)d_in[0];
    const float* degrad     = (const float*)d_in[1];
    const float* weight     = (const float*)d_in[2];
    const float* om_weight  = (const float*)d_in[3];
    const float* om_bias    = (const float*)d_in[4];
    float* out = (float*)d_out;

    cudaFuncSetAttribute(om_gemm, cudaFuncAttributeMaxDynamicSharedMemorySize, OMH_TOT);
    cudaFuncSetAttribute(deform, cudaFuncAttributeMaxDynamicSharedMemorySize, SM_TOT);

    transpose_nhwc2<<<BB * HH, 256>>>(input_feat, degrad);
    transpose_w<<<(9 * 2 * 2048 + 255) / 256, 256>>>(weight);
    transpose_omw<<<(9*16*4*32 + 255) / 256, 256>>>(om_weight);
    om_gemm<<<BB * 64, 256, OMH_TOT>>>(om_bias);
    deform<<<BB * 64, 256, SM_TOT>>>(out);
}

// round 15
// speedup vs baseline: 1.3530x; 1.1792x over previous
#include <cuda_runtime.h>
#include <cstdint>

#define BB 8
#define CC 64
#define HH 64
#define WW 64
#define OO 64
#define HWT (HH*WW)
#define JJ 27

// tf32 round (keeps top 10 mantissa bits)
__device__ __forceinline__ float tf32r(float x) {
    unsigned u;
    asm("cvt.rna.tf32.f32 %0, %1;" : "=r"(u) : "f"(x));
    return __uint_as_float(u);
}

// mma.sync m16n8k8 tf32: D += A*B (fp32 accum)
#define MMA8(D, A0, A1, A2, A3, B0, B1)                                   \
    asm volatile("mma.sync.aligned.m16n8k8.row.col.f32.tf32.tf32.f32 "     \
        "{%0,%1,%2,%3}, {%4,%5,%6,%7}, {%8,%9}, {%0,%1,%2,%3};"            \
        : "+f"((D)[0]), "+f"((D)[1]), "+f"((D)[2]), "+f"((D)[3])           \
        : "r"(A0), "r"(A1), "r"(A2), "r"(A3), "r"(B0), "r"(B1))

// Scratch (device globals: no allocation allowed)
__device__ float  g_nhwc2[BB*HH*WW*128];   // concat(feat, degrad) NHWC, 128 ch
__device__ float  g_om[BB*JJ*HWT];         // offset/mask conv output
// deform weights, hi-only tf32, nt-pair-interleaved B frags:
// flat float2 idx = ((((k*8+s)*2+wn)*2+ntp)*32+lane)*2 + nt01
__device__ __align__(16) float2 g_wtB[9*8*2*2*32*2];
// om weights, hi-only tf32, nt-interleaved:
// flat float2 idx = ((((k*16+sg)*2+wn)*32)+lane)*2 + nt
__device__ __align__(16) float2 g_omB[9*16*2*32*2];

// ---------------------------------------------------------------------------
// Kernel 1: NCHW feat+degrad -> g_nhwc2[b][y][x][128]. One block per (b,h).
// ---------------------------------------------------------------------------
__global__ __launch_bounds__(256) void transpose_nhwc2(const float* __restrict__ feat,
                                                       const float* __restrict__ deg) {
    int bh = blockIdx.x;
    int b = bh / HH, h = bh % HH;
    __shared__ float tile[128][WW + 1];
    for (int i = threadIdx.x; i < 128 * WW; i += 256) {
        int c = i >> 6, w = i & 63;
        const float* src = (c < 64) ? feat : deg;
        tile[c][w] = src[(((size_t)b * 64 + (c & 63)) * HH + h) * WW + w];
    }
    __syncthreads();
    float* dst = g_nhwc2 + (((size_t)b * HH + h) * WW) * 128;
    for (int i = threadIdx.x; i < 128 * WW; i += 256) {
        int w = i >> 7, c = i & 127;
        dst[w * 128 + c] = tile[c][w];
    }
}

// ---------------------------------------------------------------------------
// Kernel 2a: deform weight (O,C,3,3) -> g_wtB (hi tf32, nt-pair interleaved).
// ---------------------------------------------------------------------------
__global__ void transpose_w(const float* __restrict__ w) {
    int i = blockIdx.x * blockDim.x + threadIdx.x;
    if (i >= 9*8*2*2*32*2) return;
    int nt01 = i & 1;
    int r = i >> 1;
    int lane = r & 31; r >>= 5;
    int ntp = r & 1;   r >>= 1;
    int wn = r & 1;    r >>= 1;
    int s = r & 7;
    int k = r >> 3;
    int ntf = wn*4 + ntp*2 + nt01;       // 0..7 (o-tile)
    int o = ntf*8 + (lane >> 2);
    int c0 = s*8 + (lane & 3)*2;
    float v0 = w[(o*CC + c0)*9 + k];
    float v1 = w[(o*CC + c0 + 1)*9 + k];
    g_wtB[i] = make_float2(tf32r(v0), tf32r(v1));
}

// ---------------------------------------------------------------------------
// Kernel 2b: om_weight (27,128,3,3) -> g_omB (hi tf32, nt interleaved).
// j = (wn*2+nt)*8 + lane/4 (padded to 32); b0 = ch (s*8+lane%4), b1 = ch+4.
// ---------------------------------------------------------------------------
__global__ void transpose_omw(const float* __restrict__ omw) {
    int i = blockIdx.x * blockDim.x + threadIdx.x;
    if (i >= 9*16*2*32*2) return;
    int nt = i & 1;
    int r = i >> 1;
    int lane = r & 31; r >>= 5;
    int wn = r & 1;    r >>= 1;
    int s = r & 15;
    int k = r >> 4;
    int j = (wn*2 + nt)*8 + (lane >> 2);
    int c = s*8 + (lane & 3);
    float v0 = 0.f, v1 = 0.f;
    if (j < JJ) {
        v0 = omw[(j*128 + c)*9 + k];
        v1 = omw[(j*128 + c + 4)*9 + k];
    }
    g_omB[i] = make_float2(tf32r(v0), tf32r(v1));
}

// ---------------------------------------------------------------------------
// Kernel 3: om conv, stationary-halo tf32 GEMM, 8x8 px tiles + 64-ch chunks.
// B per (k,s): single uint4 LDG.128 (both nt fragments).
// ---------------------------------------------------------------------------
#define OMH_TOT (10*10*64*4)   // 25600 bytes

__global__ __launch_bounds__(256, 4) void om_gemm(const float* __restrict__ omb) {
    extern __shared__ float sh[];
    int bi = blockIdx.x;            // 512 blocks: b(8) x tY(8) x tX(8)
    int b  = bi >> 6;
    int tY = (bi >> 3) & 7;
    int tX = bi & 7;

    int t = threadIdx.x;
    int lane = t & 31;
    int wrp = t >> 5;
    int wm = wrp >> 1, wn = wrp & 1;   // 4 M-tiles x 2 N-halves
    int g = lane >> 2, tg = lane & 3;

    const float4* img = (const float4*)(g_nhwc2 + (size_t)b * HWT * 128);

    float d[2][4];
#pragma unroll
    for (int n = 0; n < 2; n++)
#pragma unroll
        for (int e = 0; e < 4; e++) d[n][e] = 0.f;

#pragma unroll
    for (int cc = 0; cc < 2; cc++) {
        if (cc) __syncthreads();
        // Halo load: 10x10 px, 64 ch chunk, swizzle c' = c ^ ((hx&7)<<2)
        for (int i = t; i < 10*10*16; i += 256) {
            int q  = i & 15;
            int hx = (i >> 4) % 10;
            int hy = i / 160;
            int gy = tY*8 + hy - 1, gx = tX*8 + hx - 1;
            float4 v = make_float4(0.f, 0.f, 0.f, 0.f);
            if (gy >= 0 && gy < HH && gx >= 0 && gx < WW)
                v = img[(gy*WW + gx)*32 + cc*16 + q];
            v.x = tf32r(v.x); v.y = tf32r(v.y); v.z = tf32r(v.z); v.w = tf32r(v.w);
            int c = (q*4) ^ ((hx & 7) << 2);
            *(float4*)&sh[(hy*10 + hx)*64 + c] = v;
        }
        __syncthreads();

        for (int k = 0; k < 9; k++) {
            int ky = k/3 - 1, kx = k%3 - 1;
            int hy = wm*2 + 1 + ky;
            int hx = g + 1 + kx;
            int sw = (hx & 7) << 2;
            const float* arow = sh + (hy*10 + hx)*64;   // a1/a3 at +640 (next row)
            const uint4* Bg = (const uint4*)(g_omB + (size_t)k * 2048);
#pragma unroll
            for (int s = 0; s < 8; s++) {
                int cb = s*8 + tg;
                int c0 = cb ^ sw;
                int c4 = (cb + 4) ^ sw;
                uint32_t a0 = __float_as_uint(arow[c0]);
                uint32_t a2 = __float_as_uint(arow[c4]);
                uint32_t a1 = __float_as_uint(arow[640 + c0]);
                uint32_t a3 = __float_as_uint(arow[640 + c4]);
                int sg = cc*8 + s;
                uint4 bb = __ldg(&Bg[(sg*2 + wn)*32 + lane]);
                MMA8(d[0], a0, a1, a2, a3, bb.x, bb.y);
                MMA8(d[1], a0, a1, a2, a3, bb.z, bb.w);
            }
        }
    }

    // Epilogue: rows = px (gy, gy+1), cols j = (wn*2+nt)*8 + 2tg
    {
        int gy = tY*8 + wm*2;
        int gx = tX*8 + g;
#pragma unroll
        for (int nt = 0; nt < 2; nt++) {
            int j = (wn*2 + nt)*8 + tg*2;
            size_t base = ((size_t)b * JJ + j) * HWT + gy * WW + gx;
            if (j < JJ) {
                float bj = omb[j];
                g_om[base]      = d[nt][0] + bj;
                g_om[base + WW] = d[nt][2] + bj;
            }
            if (j + 1 < JJ) {
                float bj = omb[j + 1];
                g_om[base + HWT]      = d[nt][1] + bj;
                g_om[base + HWT + WW] = d[nt][3] + bj;
            }
        }
    }
}

// ---------------------------------------------------------------------------
// Kernel 4: deformable conv, 2-pass tf32 (ah*bh + al*bh), 8x8 px tiles,
// all-tap metadata precomputed, B via 2x LDG.128 per (s,wn).
// ---------------------------------------------------------------------------
#define SM_PQ  0
#define SM_WQ  9216
#define SM_AHI 18432
#define SM_ALO (SM_AHI + 4*8*528)
#define SM_TOT (SM_ALO + 4*8*528)

__global__ __launch_bounds__(256, 4) void deform(float* __restrict__ out) {
    extern __shared__ char sm[];
    int bi = blockIdx.x;            // 512 blocks: b(8) x tY(8) x tX(8)
    int b  = bi >> 6;
    int tY = (bi >> 3) & 7;
    int tX = bi & 7;

    int t = threadIdx.x;
    int lane = t & 31;
    int wrp = t >> 5;
    int wm = wrp >> 1, wn = wrp & 1;

    int4*   s_pq = (int4*)(sm + SM_PQ);     // [9][64]
    float4* s_wq = (float4*)(sm + SM_WQ);   // [9][64]

    const float*  omb_  = g_om + (size_t)b * JJ * HWT;
    const float4* imgf4 = (const float4*)(g_nhwc2 + (size_t)b * HWT * 128);

    int q = t & 15, pxs = t >> 4;
    int s_smp = q >> 1;
    int lnc = (q & 1) * 2;

    float d[4][4];
#pragma unroll
    for (int n = 0; n < 4; n++)
#pragma unroll
        for (int e = 0; e < 4; e++) d[n][e] = 0.f;

    // Metadata for ALL 9 taps upfront
    for (int i = t; i < 9*64; i += 256) {
        int k = i >> 6, px = i & 63;
        int gy = tY*8 + (px >> 3), gx = tX*8 + (px & 7);
        int p = gy * WW + gx;
        float dy = omb_[(2 * k) * HWT + p];
        float dx = omb_[(2 * k + 1) * HWT + p];
        float mv = omb_[(18 + k) * HWT + p];
        float m = 1.f / (1.f + __expf(-mv));
        float y = (float)(gy - 1 + k / 3) + dy;
        float x = (float)(gx - 1 + k % 3) + dx;
        float yf = floorf(y), xf = floorf(x);
        int yi = (int)yf, xi = (int)xf;
        float wy = y - yf, wx = x - xf;
        bool vy0 = (yi >= 0) && (yi < HH);
        bool vy1 = (yi >= -1) && (yi < HH - 1);
        bool vx0 = (xi >= 0) && (xi < WW);
        bool vx1 = (xi >= -1) && (xi < WW - 1);
        float w00 = (vy0 && vx0) ? (1.f - wy) * (1.f - wx) * m : 0.f;
        float w01 = (vy0 && vx1) ? (1.f - wy) * wx * m : 0.f;
        float w10 = (vy1 && vx0) ? wy * (1.f - wx) * m : 0.f;
        float w11 = (vy1 && vx1) ? wy * wx * m : 0.f;
        int y0c = min(max(yi, 0), HH - 1), y1c = min(max(yi + 1, 0), HH - 1);
        int x0c = min(max(xi, 0), WW - 1), x1c = min(max(xi + 1, 0), WW - 1);
        s_pq[i] = make_int4(y0c * WW + x0c, y0c * WW + x1c,
                            y1c * WW + x0c, y1c * WW + x1c);
        s_wq[i] = make_float4(w00, w01, w10, w11);
    }
    __syncthreads();

    for (int k = 0; k < 9; k++) {
        if (k) __syncthreads();

        // Sampling (coalesced over channels) + hi/lo split, fragment STS
#pragma unroll
        for (int j = 0; j < 4; j++) {
            int px = pxs * 4 + j;
            int4 pq = s_pq[k*64 + px];
            float4 wq = s_wq[k*64 + px];
            float a0 = 0.f, a1 = 0.f, a2 = 0.f, a3 = 0.f;
            float4 v;
            v = imgf4[pq.x * 32 + q];
            a0 = fmaf(wq.x, v.x, a0); a1 = fmaf(wq.x, v.y, a1);
            a2 = fmaf(wq.x, v.z, a2); a3 = fmaf(wq.x, v.w, a3);
            v = imgf4[pq.y * 32 + q];
            a0 = fmaf(wq.y, v.x, a0); a1 = fmaf(wq.y, v.y, a1);
            a2 = fmaf(wq.y, v.z, a2); a3 = fmaf(wq.y, v.w, a3);
            v = imgf4[pq.z * 32 + q];
            a0 = fmaf(wq.z, v.x, a0); a1 = fmaf(wq.z, v.y, a1);
            a2 = fmaf(wq.z, v.z, a2); a3 = fmaf(wq.z, v.w, a3);
            v = imgf4[pq.w * 32 + q];
            a0 = fmaf(wq.w, v.x, a0); a1 = fmaf(wq.w, v.y, a1);
            a2 = fmaf(wq.w, v.z, a2); a3 = fmaf(wq.w, v.w, a3);

            float h0 = tf32r(a0), h1 = tf32r(a1), h2 = tf32r(a2), h3 = tf32r(a3);
            float l0 = tf32r(a0 - h0), l1 = tf32r(a1 - h1);
            float l2 = tf32r(a2 - h2), l3 = tf32r(a3 - h3);

            int mt = px >> 4;
            int r = px & 7;
            int high = (px >> 3) & 1;
            int fo = (mt * 8 + s_smp) * 528 + high * 8;
            int la = (r * 4 + lnc) * 16;
            *(float2*)(sm + SM_AHI + fo + la)      = make_float2(h0, h1);
            *(float2*)(sm + SM_AHI + fo + la + 16) = make_float2(h2, h3);
            *(float2*)(sm + SM_ALO + fo + la)      = make_float2(l0, l1);
            *(float2*)(sm + SM_ALO + fo + la + 16) = make_float2(l2, l3);
        }
        __syncthreads();

        // 2-pass GEMM (ah*bh + al*bh), B via 2x LDG.128 per (s,wn)
        {
            const char* Ah = sm + SM_AHI;
            const char* Al = sm + SM_ALO;
            const uint4* Bg = (const uint4*)g_wtB;
#pragma unroll
            for (int s = 0; s < 8; s++) {
                int f0 = (wm * 8 + s) * 528 + lane * 16;
                uint4 ah = *(const uint4*)(Ah + f0);
                uint4 al = *(const uint4*)(Al + f0);
                int bbase = (((k*8 + s)*2 + wn)*2)*32 + lane;
                uint4 b0 = __ldg(&Bg[bbase]);
                uint4 b1 = __ldg(&Bg[bbase + 32]);
                MMA8(d[0], ah.x, ah.z, ah.y, ah.w, b0.x, b0.y);
                MMA8(d[0], al.x, al.z, al.y, al.w, b0.x, b0.y);
                MMA8(d[1], ah.x, ah.z, ah.y, ah.w, b0.z, b0.w);
                MMA8(d[1], al.x, al.z, al.y, al.w, b0.z, b0.w);
                MMA8(d[2], ah.x, ah.z, ah.y, ah.w, b1.x, b1.y);
                MMA8(d[2], al.x, al.z, al.y, al.w, b1.x, b1.y);
                MMA8(d[3], ah.x, ah.z, ah.y, ah.w, b1.z, b1.w);
                MMA8(d[3], al.x, al.z, al.y, al.w, b1.z, b1.w);
            }
        }
    }

    // Epilogue: direct out writes (B,O,H,W)
    {
        int pxb = wm * 16 + (lane >> 2);
        int gy0 = tY * 8 + (pxb >> 3), gx0 = tX * 8 + (pxb & 7);
#pragma unroll
        for (int nt = 0; nt < 4; nt++) {
            int o = wn * 32 + nt * 8 + (lane & 3) * 2;
            size_t base = ((size_t)b * OO + o) * HWT;
            out[base + gy0 * WW + gx0]             = d[nt][0];
            out[base + HWT + gy0 * WW + gx0]       = d[nt][1];
            out[base + (gy0 + 1) * WW + gx0]       = d[nt][2];
            out[base + HWT + (gy0 + 1) * WW + gx0] = d[nt][3];
        }
    }
}

// ---------------------------------------------------------------------------
extern "C" void kernel_launch(void* const* d_in, const int* in_sizes, int n_in,
                              void* d_out, int out_size) {
    const float* input_feat = (const float*)d_in[0];
    const float* degrad     = (const float*)d_in[1];
    const float* weight     = (const float*)d_in[2];
    const float* om_weight  = (const float*)d_in[3];
    const float* om_bias    = (const float*)d_in[4];
    float* out = (float*)d_out;

    cudaFuncSetAttribute(om_gemm, cudaFuncAttributeMaxDynamicSharedMemorySize, OMH_TOT);
    cudaFuncSetAttribute(deform, cudaFuncAttributeMaxDynamicSharedMemorySize, SM_TOT);

    transpose_nhwc2<<<BB * HH, 256>>>(input_feat, degrad);
    transpose_w<<<(9*8*2*2*32*2 + 255) / 256, 256>>>(weight);
    transpose_omw<<<(9*16*2*32*2 + 255) / 256, 256>>>(om_weight);
    om_gemm<<<BB * 64, 256, OMH_TOT>>>(om_bias);
    deform<<<BB * 64, 256, SM_TOT>>>(out);
}

// round 16
// speedup vs baseline: 1.4063x; 1.0394x over previous
#include <cuda_runtime.h>
#include <cstdint>

#define BB 8
#define CC 64
#define HH 64
#define WW 64
#define OO 64
#define HWT (HH*WW)
#define JJ 27

// tf32 round (keeps top 10 mantissa bits)
__device__ __forceinline__ float tf32r(float x) {
    unsigned u;
    asm("cvt.rna.tf32.f32 %0, %1;" : "=r"(u) : "f"(x));
    return __uint_as_float(u);
}

// mma.sync m16n8k8 tf32: D += A*B (fp32 accum)
#define MMA8(D, A0, A1, A2, A3, B0, B1)                                   \
    asm volatile("mma.sync.aligned.m16n8k8.row.col.f32.tf32.tf32.f32 "     \
        "{%0,%1,%2,%3}, {%4,%5,%6,%7}, {%8,%9}, {%0,%1,%2,%3};"            \
        : "+f"((D)[0]), "+f"((D)[1]), "+f"((D)[2]), "+f"((D)[3])           \
        : "r"(A0), "r"(A1), "r"(A2), "r"(A3), "r"(B0), "r"(B1))

// Scratch (device globals: no allocation allowed)
// g_nhwc2 channel storage is PERMUTED within each 8-group: channel w stored
// at in-group offset f(w) = 2*(w&3) + (w>>2); offset p holds w(p)=(p>>1)+(p&1)*4.
__device__ float  g_nhwc2[BB*HH*WW*128];
__device__ float  g_om[BB*JJ*HWT];
// deform weights, hi-only tf32, nt-pair-interleaved B frags
__device__ __align__(16) float2 g_wtB[9*8*2*2*32*2];
// om weights, hi-only tf32, nt-interleaved
__device__ __align__(16) float2 g_omB[9*16*2*32*2];

// ---------------------------------------------------------------------------
// Kernel 1: NCHW feat+degrad -> g_nhwc2 (channel-permuted NHWC).
// ---------------------------------------------------------------------------
__global__ __launch_bounds__(256) void transpose_nhwc2(const float* __restrict__ feat,
                                                       const float* __restrict__ deg) {
    int bh = blockIdx.x;
    int b = bh / HH, h = bh % HH;
    __shared__ float tile[128][WW + 1];
    for (int i = threadIdx.x; i < 128 * WW; i += 256) {
        int c = i >> 6, w = i & 63;
        const float* src = (c < 64) ? feat : deg;
        tile[c][w] = src[(((size_t)b * 64 + (c & 63)) * HH + h) * WW + w];
    }
    __syncthreads();
    float* dst = g_nhwc2 + (((size_t)b * HH + h) * WW) * 128;
    for (int i = threadIdx.x; i < 128 * WW; i += 256) {
        int w = i >> 7, c = i & 127;
        int cw = c & 7;
        int pc = (c & ~7) | (2 * (cw & 3) + (cw >> 2));   // permuted position
        dst[w * 128 + pc] = tile[c][w];
    }
}

// ---------------------------------------------------------------------------
// Kernel 2a: deform weight (O,C,3,3) -> g_wtB (hi tf32, nt-pair interleaved).
// (original channel indices — storage permutation lives only in g_nhwc2)
// ---------------------------------------------------------------------------
__global__ void transpose_w(const float* __restrict__ w) {
    int i = blockIdx.x * blockDim.x + threadIdx.x;
    if (i >= 9*8*2*2*32*2) return;
    int nt01 = i & 1;
    int r = i >> 1;
    int lane = r & 31; r >>= 5;
    int ntp = r & 1;   r >>= 1;
    int wn = r & 1;    r >>= 1;
    int s = r & 7;
    int k = r >> 3;
    int ntf = wn*4 + ntp*2 + nt01;
    int o = ntf*8 + (lane >> 2);
    int c0 = s*8 + (lane & 3)*2;
    float v0 = w[(o*CC + c0)*9 + k];
    float v1 = w[(o*CC + c0 + 1)*9 + k];
    g_wtB[i] = make_float2(tf32r(v0), tf32r(v1));
}

// ---------------------------------------------------------------------------
// Kernel 2b: om_weight (27,128,3,3) -> g_omB (hi tf32, nt interleaved).
// ---------------------------------------------------------------------------
__global__ void transpose_omw(const float* __restrict__ omw) {
    int i = blockIdx.x * blockDim.x + threadIdx.x;
    if (i >= 9*16*2*32*2) return;
    int nt = i & 1;
    int r = i >> 1;
    int lane = r & 31; r >>= 5;
    int wn = r & 1;    r >>= 1;
    int s = r & 15;
    int k = r >> 4;
    int j = (wn*2 + nt)*8 + (lane >> 2);
    int c = s*8 + (lane & 3);
    float v0 = 0.f, v1 = 0.f;
    if (j < JJ) {
        v0 = omw[(j*128 + c)*9 + k];
        v1 = omw[(j*128 + c + 4)*9 + k];
    }
    g_omB[i] = make_float2(tf32r(v0), tf32r(v1));
}

// ---------------------------------------------------------------------------
// Kernel 3: om conv, stationary-halo tf32 GEMM, stride-72 rows (no XOR),
// A fragments = 2x LDS.64 per (k,s) thanks to permuted channel storage.
// ---------------------------------------------------------------------------
#define OMH_TOT (10*10*72*4)   // 28800 bytes

__global__ __launch_bounds__(256, 4) void om_gemm(const float* __restrict__ omb) {
    extern __shared__ float sh[];
    int bi = blockIdx.x;            // 512 blocks: b(8) x tY(8) x tX(8)
    int b  = bi >> 6;
    int tY = (bi >> 3) & 7;
    int tX = bi & 7;

    int t = threadIdx.x;
    int lane = t & 31;
    int wrp = t >> 5;
    int wm = wrp >> 1, wn = wrp & 1;   // 4 M-tiles x 2 N-halves
    int g = lane >> 2, tg = lane & 3;

    const float4* img = (const float4*)(g_nhwc2 + (size_t)b * HWT * 128);

    float d[2][4];
#pragma unroll
    for (int n = 0; n < 2; n++)
#pragma unroll
        for (int e = 0; e < 4; e++) d[n][e] = 0.f;

#pragma unroll
    for (int cc = 0; cc < 2; cc++) {
        if (cc) __syncthreads();
        // Halo load: 10x10 px, 64-ch chunk (already permuted in gmem), row stride 72
        for (int i = t; i < 10*10*16; i += 256) {
            int q  = i & 15;
            int hx = (i >> 4) % 10;
            int hy = i / 160;
            int gy = tY*8 + hy - 1, gx = tX*8 + hx - 1;
            float4 v = make_float4(0.f, 0.f, 0.f, 0.f);
            if (gy >= 0 && gy < HH && gx >= 0 && gx < WW)
                v = img[(gy*WW + gx)*32 + cc*16 + q];
            v.x = tf32r(v.x); v.y = tf32r(v.y); v.z = tf32r(v.z); v.w = tf32r(v.w);
            *(float4*)&sh[(hy*10 + hx)*72 + q*4] = v;
        }
        __syncthreads();

        for (int k = 0; k < 9; k++) {
            int ky = k/3 - 1, kx = k%3 - 1;
            int hy = wm*2 + 1 + ky;
            int hx = g + 1 + kx;
            const float* arow = sh + (hy*10 + hx)*72 + tg*2;   // a1/a3 at +720
            const uint4* Bg = (const uint4*)(g_omB + (size_t)k * 2048);
#pragma unroll
            for (int s = 0; s < 8; s++) {
                float2 p0 = *(const float2*)&arow[s*8];
                float2 p1 = *(const float2*)&arow[720 + s*8];
                uint32_t a0 = __float_as_uint(p0.x);
                uint32_t a2 = __float_as_uint(p0.y);
                uint32_t a1 = __float_as_uint(p1.x);
                uint32_t a3 = __float_as_uint(p1.y);
                int sg = cc*8 + s;
                uint4 bb = __ldg(&Bg[(sg*2 + wn)*32 + lane]);
                MMA8(d[0], a0, a1, a2, a3, bb.x, bb.y);
                MMA8(d[1], a0, a1, a2, a3, bb.z, bb.w);
            }
        }
    }

    // Epilogue: rows = px (gy, gy+1), cols j = (wn*2+nt)*8 + 2tg
    {
        int gy = tY*8 + wm*2;
        int gx = tX*8 + g;
#pragma unroll
        for (int nt = 0; nt < 2; nt++) {
            int j = (wn*2 + nt)*8 + tg*2;
            size_t base = ((size_t)b * JJ + j) * HWT + gy * WW + gx;
            if (j < JJ) {
                float bj = omb[j];
                g_om[base]      = d[nt][0] + bj;
                g_om[base + WW] = d[nt][2] + bj;
            }
            if (j + 1 < JJ) {
                float bj = omb[j + 1];
                g_om[base + HWT]      = d[nt][1] + bj;
                g_om[base + HWT + WW] = d[nt][3] + bj;
            }
        }
    }
}

// ---------------------------------------------------------------------------
// Kernel 4: deformable conv, 2-pass tf32, 8x8 px tiles, all-tap metadata,
// sampler remapped for permuted channels, MMAs reordered (ah block, al block).
// ---------------------------------------------------------------------------
#define SM_PQ  0
#define SM_WQ  9216
#define SM_AHI 18432
#define SM_ALO (SM_AHI + 4*8*528)
#define SM_TOT (SM_ALO + 4*8*528)

__global__ __launch_bounds__(256, 4) void deform(float* __restrict__ out) {
    extern __shared__ char sm[];
    int bi = blockIdx.x;            // 512 blocks: b(8) x tY(8) x tX(8)
    int b  = bi >> 6;
    int tY = (bi >> 3) & 7;
    int tX = bi & 7;

    int t = threadIdx.x;
    int lane = t & 31;
    int wrp = t >> 5;
    int wm = wrp >> 1, wn = wrp & 1;

    int4*   s_pq = (int4*)(sm + SM_PQ);     // [9][64]
    float4* s_wq = (float4*)(sm + SM_WQ);   // [9][64]

    const float*  omb_  = g_om + (size_t)b * JJ * HWT;
    const float4* imgf4 = (const float4*)(g_nhwc2 + (size_t)b * HWT * 128);

    int q = t & 15, pxs = t >> 4;
    int s_smp = q >> 1;
    int tga = q & 1;                 // first fragment lane-chunk; second = tga+2

    float d[4][4];
#pragma unroll
    for (int n = 0; n < 4; n++)
#pragma unroll
        for (int e = 0; e < 4; e++) d[n][e] = 0.f;

    // Metadata for ALL 9 taps upfront
    for (int i = t; i < 9*64; i += 256) {
        int k = i >> 6, px = i & 63;
        int gy = tY*8 + (px >> 3), gx = tX*8 + (px & 7);
        int p = gy * WW + gx;
        float dy = omb_[(2 * k) * HWT + p];
        float dx = omb_[(2 * k + 1) * HWT + p];
        float mv = omb_[(18 + k) * HWT + p];
        float m = 1.f / (1.f + __expf(-mv));
        float y = (float)(gy - 1 + k / 3) + dy;
        float x = (float)(gx - 1 + k % 3) + dx;
        float yf = floorf(y), xf = floorf(x);
        int yi = (int)yf, xi = (int)xf;
        float wy = y - yf, wx = x - xf;
        bool vy0 = (yi >= 0) && (yi < HH);
        bool vy1 = (yi >= -1) && (yi < HH - 1);
        bool vx0 = (xi >= 0) && (xi < WW);
        bool vx1 = (xi >= -1) && (xi < WW - 1);
        float w00 = (vy0 && vx0) ? (1.f - wy) * (1.f - wx) * m : 0.f;
        float w01 = (vy0 && vx1) ? (1.f - wy) * wx * m : 0.f;
        float w10 = (vy1 && vx0) ? wy * (1.f - wx) * m : 0.f;
        float w11 = (vy1 && vx1) ? wy * wx * m : 0.f;
        int y0c = min(max(yi, 0), HH - 1), y1c = min(max(yi + 1, 0), HH - 1);
        int x0c = min(max(xi, 0), WW - 1), x1c = min(max(xi + 1, 0), WW - 1);
        s_pq[i] = make_int4(y0c * WW + x0c, y0c * WW + x1c,
                            y1c * WW + x0c, y1c * WW + x1c);
        s_wq[i] = make_float4(w00, w01, w10, w11);
    }
    __syncthreads();

    for (int k = 0; k < 9; k++) {
        if (k) __syncthreads();

        // Sampling + hi/lo split. Permuted storage: float4 at offset 4q holds
        // channels {8s+0,8s+4,8s+1,8s+5} (q even) / {8s+2,8s+6,8s+3,8s+7} (q odd)
        // -> pairs (x,z) to lane-chunk tga, (y,w) to tga+2.
#pragma unroll
        for (int j = 0; j < 4; j++) {
            int px = pxs * 4 + j;
            int4 pq = s_pq[k*64 + px];
            float4 wq = s_wq[k*64 + px];
            float a0 = 0.f, a1 = 0.f, a2 = 0.f, a3 = 0.f;
            float4 v;
            v = imgf4[pq.x * 32 + q];
            a0 = fmaf(wq.x, v.x, a0); a1 = fmaf(wq.x, v.y, a1);
            a2 = fmaf(wq.x, v.z, a2); a3 = fmaf(wq.x, v.w, a3);
            v = imgf4[pq.y * 32 + q];
            a0 = fmaf(wq.y, v.x, a0); a1 = fmaf(wq.y, v.y, a1);
            a2 = fmaf(wq.y, v.z, a2); a3 = fmaf(wq.y, v.w, a3);
            v = imgf4[pq.z * 32 + q];
            a0 = fmaf(wq.z, v.x, a0); a1 = fmaf(wq.z, v.y, a1);
            a2 = fmaf(wq.z, v.z, a2); a3 = fmaf(wq.z, v.w, a3);
            v = imgf4[pq.w * 32 + q];
            a0 = fmaf(wq.w, v.x, a0); a1 = fmaf(wq.w, v.y, a1);
            a2 = fmaf(wq.w, v.z, a2); a3 = fmaf(wq.w, v.w, a3);

            float h0 = tf32r(a0), h1 = tf32r(a1), h2 = tf32r(a2), h3 = tf32r(a3);
            float l0 = tf32r(a0 - h0), l1 = tf32r(a1 - h1);
            float l2 = tf32r(a2 - h2), l3 = tf32r(a3 - h3);

            int mt = px >> 4;
            int r = px & 7;
            int high = (px >> 3) & 1;
            int fo = (mt * 8 + s_smp) * 528 + high * 8;
            int la1 = (r * 4 + tga) * 16;
            int la2 = la1 + 32;
            *(float2*)(sm + SM_AHI + fo + la1) = make_float2(h0, h2);
            *(float2*)(sm + SM_AHI + fo + la2) = make_float2(h1, h3);
            *(float2*)(sm + SM_ALO + fo + la1) = make_float2(l0, l2);
            *(float2*)(sm + SM_ALO + fo + la2) = make_float2(l1, l3);
        }
        __syncthreads();

        // 2-pass GEMM: ah block then al block (dependency distance 4)
        {
            const char* Ah = sm + SM_AHI;
            const char* Al = sm + SM_ALO;
            const uint4* Bg = (const uint4*)g_wtB;
#pragma unroll
            for (int s = 0; s < 8; s++) {
                int f0 = (wm * 8 + s) * 528 + lane * 16;
                uint4 ah = *(const uint4*)(Ah + f0);
                uint4 al = *(const uint4*)(Al + f0);
                int bbase = (((k*8 + s)*2 + wn)*2)*32 + lane;
                uint4 b0 = __ldg(&Bg[bbase]);
                uint4 b1 = __ldg(&Bg[bbase + 32]);
                MMA8(d[0], ah.x, ah.z, ah.y, ah.w, b0.x, b0.y);
                MMA8(d[1], ah.x, ah.z, ah.y, ah.w, b0.z, b0.w);
                MMA8(d[2], ah.x, ah.z, ah.y, ah.w, b1.x, b1.y);
                MMA8(d[3], ah.x, ah.z, ah.y, ah.w, b1.z, b1.w);
                MMA8(d[0], al.x, al.z, al.y, al.w, b0.x, b0.y);
                MMA8(d[1], al.x, al.z, al.y, al.w, b0.z, b0.w);
                MMA8(d[2], al.x, al.z, al.y, al.w, b1.x, b1.y);
                MMA8(d[3], al.x, al.z, al.y, al.w, b1.z, b1.w);
            }
        }
    }

    // Epilogue: direct out writes (B,O,H,W)
    {
        int pxb = wm * 16 + (lane >> 2);
        int gy0 = tY * 8 + (pxb >> 3), gx0 = tX * 8 + (pxb & 7);
#pragma unroll
        for (int nt = 0; nt < 4; nt++) {
            int o = wn * 32 + nt * 8 + (lane & 3) * 2;
            size_t base = ((size_t)b * OO + o) * HWT;
            out[base + gy0 * WW + gx0]             = d[nt][0];
            out[base + HWT + gy0 * WW + gx0]       = d[nt][1];
            out[base + (gy0 + 1) * WW + gx0]       = d[nt][2];
            out[base + HWT + (gy0 + 1) * WW + gx0] = d[nt][3];
        }
    }
}

// ---------------------------------------------------------------------------
extern "C" void kernel_launch(void* const* d_in, const int* in_sizes, int n_in,
                              void* d_out, int out_size) {
    const float* input_feat = (const float*)d_in[0];
    const float* degrad     = (const float*)d_in[1];
    const float* weight     = (const float*)d_in[2];
    const float* om_weight  = (const float*)d_in[3];
    const float* om_bias    = (const float*)d_in[4];
    float* out = (float*)d_out;

    cudaFuncSetAttribute(om_gemm, cudaFuncAttributeMaxDynamicSharedMemorySize, OMH_TOT);
    cudaFuncSetAttribute(deform, cudaFuncAttributeMaxDynamicSharedMemorySize, SM_TOT);

    transpose_nhwc2<<<BB * HH, 256>>>(input_feat, degrad);
    transpose_w<<<(9*8*2*2*32*2 + 255) / 256, 256>>>(weight);
    transpose_omw<<<(9*16*2*32*2 + 255) / 256, 256>>>(om_weight);
    om_gemm<<<BB * 64, 256, OMH_TOT>>>(om_bias);
    deform<<<BB * 64, 256, SM_TOT>>>(out);
}